// round 6
// baseline (speedup 1.0000x reference)
#include <cuda_runtime.h>
#include <cuda_bf16.h>
#include <cstdint>

#define NPG   100
#define DEG   16
#define BLK1  256
#define BLK2  512
#define NGRAPH 512
#define NNODES (NGRAPH * NPG)

// P = feat @ W1^T staged between kernels (fp32, coalesced)
__device__ float P_buf[(size_t)NNODES * 100];

// ---------------- helpers ----------------
__device__ __forceinline__ uint32_t cvt_tf32(float x) {
    uint32_t r;
    asm("cvt.rna.tf32.f32 %0, %1;" : "=r"(r) : "f"(x));
    return r;
}
__device__ __forceinline__ void mma_tf32(float* acc, const uint32_t* a,
                                         uint32_t b0, uint32_t b1) {
    asm volatile("mma.sync.aligned.m16n8k8.row.col.f32.tf32.tf32.f32 "
                 "{%0,%1,%2,%3}, {%4,%5,%6,%7}, {%8,%9}, {%0,%1,%2,%3};"
                 : "+f"(acc[0]), "+f"(acc[1]), "+f"(acc[2]), "+f"(acc[3])
                 : "r"(a[0]), "r"(a[1]), "r"(a[2]), "r"(a[3]),
                   "r"(b0), "r"(b1));
}
__device__ __forceinline__ void mma_bf16(float* c, const uint32_t* a,
                                         uint32_t b0, uint32_t b1) {
    asm volatile("mma.sync.aligned.m16n8k16.row.col.f32.bf16.bf16.f32 "
                 "{%0,%1,%2,%3}, {%4,%5,%6,%7}, {%8,%9}, {%0,%1,%2,%3};"
                 : "+f"(c[0]), "+f"(c[1]), "+f"(c[2]), "+f"(c[3])
                 : "r"(a[0]), "r"(a[1]), "r"(a[2]), "r"(a[3]),
                   "r"(b0), "r"(b1));
}
__device__ __forceinline__ void split2(float x, float y,
                                       uint32_t& hi, uint32_t& lo) {
    __nv_bfloat16 hx = __float2bfloat16(x), hy = __float2bfloat16(y);
    __nv_bfloat16 lx = __float2bfloat16(x - __bfloat162float(hx));
    __nv_bfloat16 ly = __float2bfloat16(y - __bfloat162float(hy));
    hi = (uint32_t)*(uint16_t*)&hx | ((uint32_t)*(uint16_t*)&hy << 16);
    lo = (uint32_t)*(uint16_t*)&lx | ((uint32_t)*(uint16_t*)&ly << 16);
}

// ====================== kernel 1: tf32 mma.sync GEMM (R4 form) ======================
#define KP 108
#define NPAD 104
#define K1_SMEM (2 * NPAD * KP * sizeof(float))

__global__ __launch_bounds__(BLK1, 2)
void gemm1_kernel(const float* __restrict__ feat, const float* __restrict__ W1)
{
    extern __shared__ uint32_t sm1[];
    uint32_t* Bhi = sm1;
    uint32_t* Blo = sm1 + NPAD * KP;

    const int tid  = threadIdx.x;
    const int warp = tid >> 5;
    const int lane = tid & 31;
    const int qg   = lane >> 2;
    const int tig  = lane & 3;

    for (int i = tid; i < 2 * NPAD * KP; i += BLK1) sm1[i] = 0u;
    __syncthreads();

    {
        const float4* gw = (const float4*)W1;
        for (int i = tid; i < 100 * 100 / 4; i += BLK1) {
            float4 v = gw[i];
            int row = (i * 4) / 100, col = (i * 4) % 100;
            uint32_t* dh = Bhi + row * KP + col;
            uint32_t* dl = Blo + row * KP + col;
            float x[4] = { v.x, v.y, v.z, v.w };
            #pragma unroll
            for (int q = 0; q < 4; q++) {
                uint32_t h = cvt_tf32(x[q]);
                dh[q] = h;
                dl[q] = cvt_tf32(x[q] - __uint_as_float(h));
            }
        }
    }
    __syncthreads();

    const int mbase = blockIdx.x * 128 + warp * 16;
    const float* arow0 = feat + (size_t)(mbase + qg) * 100;
    const float* arow1 = feat + (size_t)(mbase + 8 + qg) * 100;

    float acc[13][4];
    #pragma unroll
    for (int nt = 0; nt < 13; nt++)
        #pragma unroll
        for (int q = 0; q < 4; q++) acc[nt][q] = 0.f;

    #pragma unroll 1
    for (int kt = 0; kt < 13; kt++) {
        const int k0 = kt * 8;
        const int kA = k0 + tig;
        const int kB = k0 + tig + 4;
        float a0f = (kA < 100) ? __ldg(arow0 + kA) : 0.f;
        float a1f = (kA < 100) ? __ldg(arow1 + kA) : 0.f;
        float a2f = (kB < 100) ? __ldg(arow0 + kB) : 0.f;
        float a3f = (kB < 100) ? __ldg(arow1 + kB) : 0.f;
        uint32_t ah[4], al[4];
        ah[0] = cvt_tf32(a0f); al[0] = cvt_tf32(a0f - __uint_as_float(ah[0]));
        ah[1] = cvt_tf32(a1f); al[1] = cvt_tf32(a1f - __uint_as_float(ah[1]));
        ah[2] = cvt_tf32(a2f); al[2] = cvt_tf32(a2f - __uint_as_float(ah[2]));
        ah[3] = cvt_tf32(a3f); al[3] = cvt_tf32(a3f - __uint_as_float(ah[3]));

        const uint32_t* bh = Bhi + qg * KP + k0 + tig;
        const uint32_t* bl = Blo + qg * KP + k0 + tig;
        #pragma unroll
        for (int nt = 0; nt < 13; nt++) {
            const int roff = nt * 8 * KP;
            uint32_t bh0 = bh[roff], bh1 = bh[roff + 4];
            uint32_t bl0 = bl[roff], bl1 = bl[roff + 4];
            mma_tf32(acc[nt], ah, bh0, bh1);
            mma_tf32(acc[nt], ah, bl0, bl1);
            mma_tf32(acc[nt], al, bh0, bh1);
        }
    }

    float* crow0 = P_buf + (size_t)(mbase + qg) * 100;
    float* crow1 = P_buf + (size_t)(mbase + 8 + qg) * 100;
    #pragma unroll
    for (int nt = 0; nt < 13; nt++) {
        int col = nt * 8 + 2 * tig;
        if (col < 100) {
            *(float2*)(crow0 + col) = make_float2(acc[nt][0], acc[nt][1]);
            *(float2*)(crow1 + col) = make_float2(acc[nt][2], acc[nt][3]);
        }
    }
}

// ====================== kernel 2: bf16 MMA GNN, 512 threads, no spills ======================
#define SP   120     // bf16 tile s-stride (halves)
#define SP32 60      // same in uint32 words
#define H1S  116     // h1 fp32 col stride

// smem byte offsets
#define B_P    0                 // [100][100] fp32 P tile
#define B_PTH  40000             // [104][120] bf16 P^T hi
#define B_PTL  64960             // [104][120] bf16 P^T lo
#define B_A    89920             // [112][120] bf16 adjacency/16
#define B_H1   116800            // [112][116] fp32 h1
#define B_W2H  168768            // [24][120] bf16
#define B_W2L  174528
#define B_STH  180288            // [24][120] bf16 sT^T hi
#define B_STL  186048
#define B_B1   191808            // [100] f32
#define B_B2   192208            // [20]
#define B_HG   192288            // [20]
#define B_Z2   192368            // [20]
#define B_Z3   192448            // [20]
#define B_V2S  192528            // [32]
#define B_V3S  192656            // [32]
#define K2_BYTES 192784

__global__ __launch_bounds__(BLK2, 1)
void gnn_rest_kernel(const int*   __restrict__ edge_src,
                     const float* __restrict__ self_feat,
                     const float* __restrict__ x3d,
                     const float* __restrict__ b1,
                     const float* __restrict__ W2, const float* __restrict__ b2,
                     const float* __restrict__ Wv2, const float* __restrict__ Wo2,
                     const float* __restrict__ g2,  const float* __restrict__ be2,
                     const float* __restrict__ Wv3, const float* __restrict__ Wo3,
                     const float* __restrict__ g3,  const float* __restrict__ be3,
                     const float* __restrict__ Wf1, const float* __restrict__ bf1,
                     const float* __restrict__ Wf2, const float* __restrict__ bf2,
                     float* __restrict__ out)
{
    extern __shared__ unsigned char sm[];
    const int g    = blockIdx.x;
    const int tid  = threadIdx.x;
    const int lane = tid & 31;
    const int warp = tid >> 5;
    const int qg   = lane >> 2;
    const int tig  = lane & 3;

    // ---- phase 0: zero tiles, load P fp32, biases ----
    {
        uint4 z = make_uint4(0, 0, 0, 0);
        uint4* p = (uint4*)(sm + B_PTH);
        for (int i = tid; i < (B_B1 - B_PTH) / 16; i += BLK2) p[i] = z;
        const float4* gp = (const float4*)(P_buf + (size_t)g * NPG * 100);
        float4* sp = (float4*)(sm + B_P);
        #pragma unroll
        for (int i = tid; i < 2500; i += BLK2) sp[i] = gp[i];
        if (tid < 100) ((float*)(sm + B_B1))[tid] = b1[tid];
        if (tid < 20)  ((float*)(sm + B_B2))[tid] = b2[tid];
        if (tid < 20)  ((float*)(sm + B_HG))[tid] = 0.f;
    }
    __syncthreads();   // S1

    // ---- phase 1 (parallel crews) ----
    if (tid < 100) {
        // adjacency A[dst][src] += 1/16 (exact in bf16)
        const int4* es = (const int4*)(edge_src + (size_t)g * NPG * DEG + tid * DEG);
        const int base = g * NPG;
        __nv_bfloat16* arow = (__nv_bfloat16*)(sm + B_A) + tid * SP;
        #pragma unroll
        for (int q = 0; q < 4; q++) {
            int4 e4 = es[q];
            int s0 = e4.x - base, s1 = e4.y - base, s2 = e4.z - base, s3 = e4.w - base;
            arow[s0] = __float2bfloat16(__bfloat162float(arow[s0]) + 0.0625f);
            arow[s1] = __float2bfloat16(__bfloat162float(arow[s1]) + 0.0625f);
            arow[s2] = __float2bfloat16(__bfloat162float(arow[s2]) + 0.0625f);
            arow[s3] = __float2bfloat16(__bfloat162float(arow[s3]) + 0.0625f);
        }
    } else if (tid < 448) {
        // P [s][d] fp32 -> PT[d][s] bf16 hi/lo
        const float* Pf = (const float*)(sm + B_P);
        __nv_bfloat16* PH = (__nv_bfloat16*)(sm + B_PTH);
        __nv_bfloat16* PL = (__nv_bfloat16*)(sm + B_PTL);
        for (int i = tid - 100; i < 10000; i += 348) {
            int s = i / 100, d = i - s * 100;
            float v = Pf[i];
            __nv_bfloat16 h = __float2bfloat16(v);
            PH[d * SP + s] = h;
            PL[d * SP + s] = __float2bfloat16(v - __bfloat162float(h));
        }
    } else {
        // warps 14,15: W2 -> bf16 hi/lo
        const float4* gw = (const float4*)W2;
        uint32_t* wh = (uint32_t*)(sm + B_W2H);
        uint32_t* wl = (uint32_t*)(sm + B_W2L);
        for (int i = tid - 448; i < 500; i += 64) {
            float4 v = gw[i];
            int row = (i * 4) / 100, col = (i * 4) % 100;
            uint32_t h0, l0, h1, l1;
            split2(v.x, v.y, h0, l0);
            split2(v.z, v.w, h1, l1);
            wh[row * SP32 + col / 2]     = h0;
            wh[row * SP32 + col / 2 + 1] = h1;
            wl[row * SP32 + col / 2]     = l0;
            wl[row * SP32 + col / 2 + 1] = l1;
        }
    }
    __syncthreads();   // S2

    // ---- MMA1 (warps 0-13): h1 = relu(A @ P + b1), streamed accumulators ----
    if (warp < 14) {
        const int m  = (warp < 7) ? warp : warp - 7;
        const int nt0 = (warp < 7) ? 0 : 7;
        const int ntN = (warp < 7) ? 7 : 6;
        const int m0 = m * 16;
        const int r0 = m0 + qg, r1 = m0 + 8 + qg;

        const uint32_t* A32 = (const uint32_t*)(sm + B_A);
        uint32_t afr[7][4];
        #pragma unroll
        for (int k = 0; k < 7; k++) {
            int i0 = r0 * SP32 + k * 8 + tig;
            int i1 = r1 * SP32 + k * 8 + tig;
            afr[k][0] = A32[i0];     afr[k][1] = A32[i1];
            afr[k][2] = A32[i0 + 4]; afr[k][3] = A32[i1 + 4];
        }
        const uint32_t* PH = (const uint32_t*)(sm + B_PTH);
        const uint32_t* PL = (const uint32_t*)(sm + B_PTL);
        float* H1 = (float*)(sm + B_H1);
        const float* b1s = (const float*)(sm + B_B1);

        #pragma unroll 1
        for (int j = 0; j < ntN; j++) {
            const int nt = nt0 + j;
            float t[4] = {0.f, 0.f, 0.f, 0.f};
            const int bb = (nt * 8 + qg) * SP32 + tig;
            #pragma unroll
            for (int k = 0; k < 7; k++)
                mma_bf16(t, afr[k], PH[bb + k * 8], PH[bb + k * 8 + 4]);
            #pragma unroll
            for (int k = 0; k < 7; k++)
                mma_bf16(t, afr[k], PL[bb + k * 8], PL[bb + k * 8 + 4]);
            const int col = nt * 8 + 2 * tig;
            if (col < 100) {
                float bx = b1s[col], by = b1s[col + 1];
                H1[r0 * H1S + col]     = fmaxf(t[0] + bx, 0.f);
                H1[r0 * H1S + col + 1] = fmaxf(t[1] + by, 0.f);
                H1[r1 * H1S + col]     = fmaxf(t[2] + bx, 0.f);
                H1[r1 * H1S + col + 1] = fmaxf(t[3] + by, 0.f);
            } else {
                H1[r0 * H1S + col] = 0.f; H1[r0 * H1S + col + 1] = 0.f;
                H1[r1 * H1S + col] = 0.f; H1[r1 * H1S + col + 1] = 0.f;
            }
        }
    } else if (warp == 14) {
        // z2 = Wo2 @ (Wv2 @ self_feat[g])
        float* vs = (float*)(sm + B_V2S);
        {
            const float4* xr = (const float4*)(self_feat + (size_t)g * 200);
            const float4* wr = (const float4*)(Wv2 + lane * 200);
            float acc = 0.f;
            #pragma unroll 5
            for (int p = 0; p < 50; p++) {
                float4 a = wr[p], b = xr[p];
                acc += a.x * b.x + a.y * b.y + a.z * b.z + a.w * b.w;
            }
            vs[lane] = acc;
        }
        __syncwarp();
        if (lane < 20) {
            const float* wo = Wo2 + lane * 32;
            float z = 0.f;
            #pragma unroll
            for (int j = 0; j < 32; j++) z += wo[j] * vs[j];
            ((float*)(sm + B_Z2))[lane] = z;
        }
    } else {
        // z3 = Wo3 @ (Wv3 @ x3d[g])
        float* vs = (float*)(sm + B_V3S);
        {
            const float4* xr = (const float4*)(x3d + (size_t)g * 100);
            const float4* wr = (const float4*)(Wv3 + lane * 100);
            float acc = 0.f;
            #pragma unroll 5
            for (int p = 0; p < 25; p++) {
                float4 a = wr[p], b = xr[p];
                acc += a.x * b.x + a.y * b.y + a.z * b.z + a.w * b.w;
            }
            vs[lane] = acc;
        }
        __syncwarp();
        if (lane < 20) {
            const float* wo = Wo3 + lane * 32;
            float z = 0.f;
            #pragma unroll
            for (int j = 0; j < 32; j++) z += wo[j] * vs[j];
            ((float*)(sm + B_Z3))[lane] = z;
        }
    }
    __syncthreads();   // S3

    // ---- MMA2 (warps 0-6): sT = h1 @ W2^T -> sT^T bf16 hi/lo ----
    if (warp < 7) {
        const int m0 = warp * 16;
        const int r0 = m0 + qg, r1 = m0 + 8 + qg;
        const float* H1 = (const float*)(sm + B_H1);
        const uint32_t* WH = (const uint32_t*)(sm + B_W2H);
        const uint32_t* WL = (const uint32_t*)(sm + B_W2L);

        uint32_t ah[7][4], al[7][4];
        #pragma unroll
        for (int k = 0; k < 7; k++) {
            int c0 = 2 * (k * 8 + tig), c1 = 2 * (k * 8 + tig + 4);
            float2 a0 = *(const float2*)(H1 + r0 * H1S + c0);
            float2 a1 = *(const float2*)(H1 + r1 * H1S + c0);
            float2 a2 = *(const float2*)(H1 + r0 * H1S + c1);
            float2 a3 = *(const float2*)(H1 + r1 * H1S + c1);
            split2(a0.x, a0.y, ah[k][0], al[k][0]);
            split2(a1.x, a1.y, ah[k][1], al[k][1]);
            split2(a2.x, a2.y, ah[k][2], al[k][2]);
            split2(a3.x, a3.y, ah[k][3], al[k][3]);
        }
        __nv_bfloat16* STH = (__nv_bfloat16*)(sm + B_STH);
        __nv_bfloat16* STL = (__nv_bfloat16*)(sm + B_STL);
        #pragma unroll 1
        for (int nt = 0; nt < 3; nt++) {
            float t[4] = {0.f, 0.f, 0.f, 0.f};
            const int bb = (nt * 8 + qg) * SP32 + tig;
            #pragma unroll
            for (int k = 0; k < 7; k++) {
                uint32_t bh0 = WH[bb + k * 8], bh1 = WH[bb + k * 8 + 4];
                uint32_t bl0 = WL[bb + k * 8], bl1 = WL[bb + k * 8 + 4];
                mma_bf16(t, ah[k], bh0, bh1);
                mma_bf16(t, ah[k], bl0, bl1);
                mma_bf16(t, al[k], bh0, bh1);
            }
            const int col = nt * 8 + 2 * tig;
            if (col < 20 && r0 < 100) {
                __nv_bfloat16 h0 = __float2bfloat16(t[0]);
                __nv_bfloat16 h1v = __float2bfloat16(t[1]);
                STH[col * SP + r0]       = h0;
                STL[col * SP + r0]       = __float2bfloat16(t[0] - __bfloat162float(h0));
                STH[(col + 1) * SP + r0] = h1v;
                STL[(col + 1) * SP + r0] = __float2bfloat16(t[1] - __bfloat162float(h1v));
            }
            if (col < 20 && r1 < 100) {
                __nv_bfloat16 h0 = __float2bfloat16(t[2]);
                __nv_bfloat16 h1v = __float2bfloat16(t[3]);
                STH[col * SP + r1]       = h0;
                STL[col * SP + r1]       = __float2bfloat16(t[2] - __bfloat162float(h0));
                STH[(col + 1) * SP + r1] = h1v;
                STL[(col + 1) * SP + r1] = __float2bfloat16(t[3] - __bfloat162float(h1v));
            }
        }
    }
    __syncthreads();   // S4

    // ---- MMA3 (warps 0-6): h2 = relu(A @ sT + b2); hg accum ----
    if (warp < 7) {
        const int m0 = warp * 16;
        const int r0 = m0 + qg, r1 = m0 + 8 + qg;
        const uint32_t* A32 = (const uint32_t*)(sm + B_A);
        const uint32_t* SH  = (const uint32_t*)(sm + B_STH);
        const uint32_t* SL  = (const uint32_t*)(sm + B_STL);
        float* shg = (float*)(sm + B_HG);
        const float* b2s = (const float*)(sm + B_B2);

        uint32_t a2[7][4];
        #pragma unroll
        for (int k = 0; k < 7; k++) {
            int i0 = r0 * SP32 + k * 8 + tig;
            int i1 = r1 * SP32 + k * 8 + tig;
            a2[k][0] = A32[i0];     a2[k][1] = A32[i1];
            a2[k][2] = A32[i0 + 4]; a2[k][3] = A32[i1 + 4];
        }
        #pragma unroll 1
        for (int nt = 0; nt < 3; nt++) {
            float t[4] = {0.f, 0.f, 0.f, 0.f};
            const int bb = (nt * 8 + qg) * SP32 + tig;
            #pragma unroll
            for (int k = 0; k < 7; k++) {
                mma_bf16(t, a2[k], SH[bb + k * 8], SH[bb + k * 8 + 4]);
                mma_bf16(t, a2[k], SL[bb + k * 8], SL[bb + k * 8 + 4]);
            }
            const int col = nt * 8 + 2 * tig;
            if (col < 20) {
                float bx = b2s[col], by = b2s[col + 1];
                float acc0 = (r0 < 100 ? fmaxf(t[0] + bx, 0.f) : 0.f)
                           + (r1 < 100 ? fmaxf(t[2] + bx, 0.f) : 0.f);
                float acc1 = (r0 < 100 ? fmaxf(t[1] + by, 0.f) : 0.f)
                           + (r1 < 100 ? fmaxf(t[3] + by, 0.f) : 0.f);
                atomicAdd(shg + col, acc0);
                atomicAdd(shg + col + 1, acc1);
            }
        }
    }
    __syncthreads();   // S5

    // ---- tail (warp 0): hg + z2 -> LN -> + z3 -> LN -> MLP ----
    if (warp == 0) {
        const float* shg = (const float*)(sm + B_HG);
        const float* z2  = (const float*)(sm + B_Z2);
        const float* z3  = (const float*)(sm + B_Z3);
        float* sVec = (float*)(sm + B_V2S);

        float y = 0.f;
        if (lane < 20) y = shg[lane] * (1.f / NPG) + z2[lane];
        float s = y;
        #pragma unroll
        for (int o = 16; o; o >>= 1) s += __shfl_xor_sync(0xffffffffu, s, o);
        float mu = s * (1.f / 20.f);
        float dd = (lane < 20) ? (y - mu) : 0.f;
        float vv = dd * dd;
        #pragma unroll
        for (int o = 16; o; o >>= 1) vv += __shfl_xor_sync(0xffffffffu, vv, o);
        float hg1 = 0.f;
        if (lane < 20)
            hg1 = dd * rsqrtf(vv * (1.f / 20.f) + 1e-5f) * g2[lane] + be2[lane];

        float y2 = (lane < 20) ? (hg1 + z3[lane]) : 0.f;
        float s2 = y2;
        #pragma unroll
        for (int o = 16; o; o >>= 1) s2 += __shfl_xor_sync(0xffffffffu, s2, o);
        float mu2 = s2 * (1.f / 20.f);
        float d2 = (lane < 20) ? (y2 - mu2) : 0.f;
        float v2s = d2 * d2;
        #pragma unroll
        for (int o = 16; o; o >>= 1) v2s += __shfl_xor_sync(0xffffffffu, v2s, o);
        float hg2 = 0.f;
        if (lane < 20)
            hg2 = d2 * rsqrtf(v2s * (1.f / 20.f) + 1e-5f) * g3[lane] + be3[lane];

        __syncwarp();
        if (lane < 20) sVec[lane] = hg2;
        __syncwarp();

        float f = 0.f;
        if (lane < 10) {
            const float* wf = Wf1 + lane * 20;
            float a = bf1[lane];
            #pragma unroll
            for (int k = 0; k < 20; k++) a += wf[k] * sVec[k];
            f = fmaxf(a, 0.f) * Wf2[lane];
        }
        #pragma unroll
        for (int o = 16; o; o >>= 1) f += __shfl_xor_sync(0xffffffffu, f, o);
        if (lane == 0) out[g] = f + bf2[0];
    }
}

// ============================ launch ============================
extern "C" void kernel_launch(void* const* d_in, const int* in_sizes, int n_in,
                              void* d_out, int out_size) {
    const float* feat      = (const float*)d_in[0];
    const int*   edge_src  = (const int*)  d_in[1];
    // d_in[2] = edge_dst: repeat(arange(N), DEG) by construction — implicit
    const float* self_feat = (const float*)d_in[3];
    const float* x3d       = (const float*)d_in[4];
    const float* W1  = (const float*)d_in[5];
    const float* b1  = (const float*)d_in[6];
    const float* W2  = (const float*)d_in[7];
    const float* b2  = (const float*)d_in[8];
    const float* Wv2 = (const float*)d_in[11];
    const float* Wo2 = (const float*)d_in[12];
    const float* g2  = (const float*)d_in[13];
    const float* be2 = (const float*)d_in[14];
    const float* Wv3 = (const float*)d_in[17];
    const float* Wo3 = (const float*)d_in[18];
    const float* g3  = (const float*)d_in[19];
    const float* be3 = (const float*)d_in[20];
    const float* Wf1 = (const float*)d_in[21];
    const float* bf1 = (const float*)d_in[22];
    const float* Wf2 = (const float*)d_in[23];
    const float* bf2 = (const float*)d_in[24];

    cudaFuncSetAttribute(gemm1_kernel,
                         cudaFuncAttributeMaxDynamicSharedMemorySize,
                         (int)K1_SMEM);
    gemm1_kernel<<<NNODES / 128, BLK1, K1_SMEM>>>(feat, W1);

    cudaFuncSetAttribute(gnn_rest_kernel,
                         cudaFuncAttributeMaxDynamicSharedMemorySize,
                         K2_BYTES);
    gnn_rest_kernel<<<NGRAPH, BLK2, K2_BYTES>>>(
        edge_src, self_feat, x3d,
        b1, W2, b2,
        Wv2, Wo2, g2, be2,
        Wv3, Wo3, g3, be3,
        Wf1, bf1, Wf2, bf2,
        (float*)d_out);
}

// round 7
// speedup vs baseline: 1.2604x; 1.2604x over previous
#include <cuda_runtime.h>
#include <cstdint>

#define NPG   100
#define DEG   16
#define BLK   256
#define NGRAPH 512
#define NNODES (NGRAPH * NPG)

// P = feat @ W1^T staged between kernels (fp32, coalesced rows of 100)
__device__ float P_buf[(size_t)NNODES * 100];

// ---------------- helpers ----------------
__device__ __forceinline__ uint32_t cvt_tf32(float x) {
    uint32_t r;
    asm("cvt.rna.tf32.f32 %0, %1;" : "=r"(r) : "f"(x));
    return r;
}
__device__ __forceinline__ void mma_tf32(float* acc, const uint32_t* a,
                                         uint32_t b0, uint32_t b1) {
    asm volatile("mma.sync.aligned.m16n8k8.row.col.f32.tf32.tf32.f32 "
                 "{%0,%1,%2,%3}, {%4,%5,%6,%7}, {%8,%9}, {%0,%1,%2,%3};"
                 : "+f"(acc[0]), "+f"(acc[1]), "+f"(acc[2]), "+f"(acc[3])
                 : "r"(a[0]), "r"(a[1]), "r"(a[2]), "r"(a[3]),
                   "r"(b0), "r"(b1));
}
__device__ __forceinline__ unsigned long long f32x2_fma(unsigned long long a,
                                                        unsigned long long b,
                                                        unsigned long long c) {
    unsigned long long d;
    asm("fma.rn.f32x2 %0, %1, %2, %3;" : "=l"(d) : "l"(a), "l"(b), "l"(c));
    return d;
}
__device__ __forceinline__ float f32x2_hsum(unsigned long long v) {
    return __uint_as_float((unsigned)(v & 0xffffffffull))
         + __uint_as_float((unsigned)(v >> 32));
}

// ====================== kernel 1: tf32 mma.sync GEMM (R4 form, unchanged) ======================
#define KP 108
#define NPAD 104
#define K1_SMEM (2 * NPAD * KP * sizeof(float))

__global__ __launch_bounds__(BLK, 2)
void gemm1_kernel(const float* __restrict__ feat, const float* __restrict__ W1)
{
    extern __shared__ uint32_t sm1[];
    uint32_t* Bhi = sm1;
    uint32_t* Blo = sm1 + NPAD * KP;

    const int tid  = threadIdx.x;
    const int warp = tid >> 5;
    const int lane = tid & 31;
    const int qg   = lane >> 2;
    const int tig  = lane & 3;

    for (int i = tid; i < 2 * NPAD * KP; i += BLK) sm1[i] = 0u;
    __syncthreads();

    {
        const float4* gw = (const float4*)W1;
        for (int i = tid; i < 100 * 100 / 4; i += BLK) {
            float4 v = gw[i];
            int row = (i * 4) / 100, col = (i * 4) % 100;
            uint32_t* dh = Bhi + row * KP + col;
            uint32_t* dl = Blo + row * KP + col;
            float x[4] = { v.x, v.y, v.z, v.w };
            #pragma unroll
            for (int q = 0; q < 4; q++) {
                uint32_t h = cvt_tf32(x[q]);
                dh[q] = h;
                dl[q] = cvt_tf32(x[q] - __uint_as_float(h));
            }
        }
    }
    __syncthreads();

    const int mbase = blockIdx.x * 128 + warp * 16;
    const float* arow0 = feat + (size_t)(mbase + qg) * 100;
    const float* arow1 = feat + (size_t)(mbase + 8 + qg) * 100;

    float acc[13][4];
    #pragma unroll
    for (int nt = 0; nt < 13; nt++)
        #pragma unroll
        for (int q = 0; q < 4; q++) acc[nt][q] = 0.f;

    #pragma unroll 1
    for (int kt = 0; kt < 13; kt++) {
        const int k0 = kt * 8;
        const int kA = k0 + tig;
        const int kB = k0 + tig + 4;
        float a0f = (kA < 100) ? __ldg(arow0 + kA) : 0.f;
        float a1f = (kA < 100) ? __ldg(arow1 + kA) : 0.f;
        float a2f = (kB < 100) ? __ldg(arow0 + kB) : 0.f;
        float a3f = (kB < 100) ? __ldg(arow1 + kB) : 0.f;
        uint32_t ah[4], al[4];
        ah[0] = cvt_tf32(a0f); al[0] = cvt_tf32(a0f - __uint_as_float(ah[0]));
        ah[1] = cvt_tf32(a1f); al[1] = cvt_tf32(a1f - __uint_as_float(ah[1]));
        ah[2] = cvt_tf32(a2f); al[2] = cvt_tf32(a2f - __uint_as_float(ah[2]));
        ah[3] = cvt_tf32(a3f); al[3] = cvt_tf32(a3f - __uint_as_float(ah[3]));

        const uint32_t* bh = Bhi + qg * KP + k0 + tig;
        const uint32_t* bl = Blo + qg * KP + k0 + tig;
        #pragma unroll
        for (int nt = 0; nt < 13; nt++) {
            const int roff = nt * 8 * KP;
            uint32_t bh0 = bh[roff], bh1 = bh[roff + 4];
            uint32_t bl0 = bl[roff], bl1 = bl[roff + 4];
            mma_tf32(acc[nt], ah, bh0, bh1);
            mma_tf32(acc[nt], ah, bl0, bl1);
            mma_tf32(acc[nt], al, bh0, bh1);
        }
    }

    float* crow0 = P_buf + (size_t)(mbase + qg) * 100;
    float* crow1 = P_buf + (size_t)(mbase + 8 + qg) * 100;
    #pragma unroll
    for (int nt = 0; nt < 13; nt++) {
        int col = nt * 8 + 2 * tig;
        if (col < 100) {
            *(float2*)(crow0 + col) = make_float2(acc[nt][0], acc[nt][1]);
            *(float2*)(crow1 + col) = make_float2(acc[nt][2], acc[nt][3]);
        }
    }
}

// ====================== kernel 2: scalar, 4 CTAs/SM, global-gather agg ======================
// smem float offsets
#define OFF_H1   0                         // [100][100] fp32 h1
#define OFF_W2   10000                     // [20][102]  fp32 W2 -> later sT[100][20]
#define OFF_B1   (OFF_W2 + 20 * 102)       // [100]
#define OFF_B2   (OFF_B1 + 100)            // [20]
#define OFF_HG   (OFF_B2 + 20)             // [20]
#define OFF_VEC  (OFF_HG + 20)             // [32]
#define OFF_SRC  (OFF_VEC + 32)            // bytes [1600]
#define K2_FLOATS (OFF_SRC + (NPG * DEG + 3) / 4)

__global__ __launch_bounds__(BLK, 4)
void gnn_rest_kernel(const int*   __restrict__ edge_src,
                     const float* __restrict__ self_feat,
                     const float* __restrict__ x3d,
                     const float* __restrict__ b1,
                     const float* __restrict__ W2, const float* __restrict__ b2,
                     const float* __restrict__ Wv2, const float* __restrict__ Wo2,
                     const float* __restrict__ g2,  const float* __restrict__ be2,
                     const float* __restrict__ Wv3, const float* __restrict__ Wo3,
                     const float* __restrict__ g3,  const float* __restrict__ be3,
                     const float* __restrict__ Wf1, const float* __restrict__ bf1,
                     const float* __restrict__ Wf2, const float* __restrict__ bf2,
                     float* __restrict__ out)
{
    extern __shared__ float smem[];
    float* sH1  = smem + OFF_H1;
    float* sW2  = smem + OFF_W2;      // sT overlays this after phase C
    float* sB1  = smem + OFF_B1;
    float* sB2  = smem + OFF_B2;
    float* shg  = smem + OFF_HG;
    float* sVec = smem + OFF_VEC;
    unsigned char* sSrc = (unsigned char*)(smem + OFF_SRC);

    const int g    = blockIdx.x;
    const int tid  = threadIdx.x;
    const int lane = tid & 31;
    const int warp = tid >> 5;

    // ---- phase 0: W2 tile, biases, edge ids ----
    {
        const float4* gw2 = (const float4*)W2;
        for (int i = tid; i < 500; i += BLK) {
            float4 v = gw2[i];
            int row = (i * 4) / 100, col = (i * 4) % 100;
            float* d = sW2 + row * 102 + col;
            d[0] = v.x; d[1] = v.y; d[2] = v.z; d[3] = v.w;
        }
        if (tid < 100) sB1[tid] = b1[tid];
        if (tid < 20)  sB2[tid] = b2[tid];
        if (tid < 20)  shg[tid] = 0.f;
        const int* es = edge_src + (size_t)g * NPG * DEG;
        const int base = g * NPG;
        for (int i = tid; i < NPG * DEG; i += BLK)
            sSrc[i] = (unsigned char)(es[i] - base);
    }
    __syncthreads();   // S0

    // ---- phase B: h1 = relu(mean_e P[src] + b1); P gathered from GLOBAL (L1/L2-hot) ----
    {
        const float4* Pg = (const float4*)(P_buf + (size_t)g * NPG * 100);  // rows of 25 float4
        const bool act = (lane < 25);
        float4 bvec = make_float4(0.f, 0.f, 0.f, 0.f);
        if (act) bvec = *(const float4*)(sB1 + 4 * lane);

        for (int n = warp; n < NPG; n += 8) {
            const uint4 w = *(const uint4*)(sSrc + n * DEG);   // broadcast
            float4 a0 = make_float4(0.f, 0.f, 0.f, 0.f);
            float4 a1 = a0, a2 = a0, a3 = a0;
            if (act) {
                #pragma unroll
                for (int b = 0; b < 4; b++) {
                    int s0 = (w.x >> (8 * b)) & 0xff;
                    int s1 = (w.y >> (8 * b)) & 0xff;
                    int s2 = (w.z >> (8 * b)) & 0xff;
                    int s3 = (w.w >> (8 * b)) & 0xff;
                    float4 v0 = __ldg(Pg + s0 * 25 + lane);
                    float4 v1 = __ldg(Pg + s1 * 25 + lane);
                    float4 v2 = __ldg(Pg + s2 * 25 + lane);
                    float4 v3 = __ldg(Pg + s3 * 25 + lane);
                    a0.x += v0.x; a0.y += v0.y; a0.z += v0.z; a0.w += v0.w;
                    a1.x += v1.x; a1.y += v1.y; a1.z += v1.z; a1.w += v1.w;
                    a2.x += v2.x; a2.y += v2.y; a2.z += v2.z; a2.w += v2.w;
                    a3.x += v3.x; a3.y += v3.y; a3.z += v3.z; a3.w += v3.w;
                }
                float4 r;
                r.x = fmaxf((a0.x + a1.x + a2.x + a3.x) * (1.f / DEG) + bvec.x, 0.f);
                r.y = fmaxf((a0.y + a1.y + a2.y + a3.y) * (1.f / DEG) + bvec.y, 0.f);
                r.z = fmaxf((a0.z + a1.z + a2.z + a3.z) * (1.f / DEG) + bvec.z, 0.f);
                r.w = fmaxf((a0.w + a1.w + a2.w + a3.w) * (1.f / DEG) + bvec.w, 0.f);
                *(float4*)(sH1 + n * 100 + 4 * lane) = r;
            }
        }
    }
    __syncthreads();   // S1

    // ---- phase C: sT = h1 @ W2^T  (acc in regs; sT overlays W2 after sync) ----
    {
        const int kk = (lane < 20) ? lane : 19;
        const unsigned long long* pb = (const unsigned long long*)(sW2 + kk * 102);
        unsigned long long acc[13];
        #pragma unroll
        for (int i = 0; i < 13; i++) acc[i] = 0ull;

        #pragma unroll 2
        for (int dp = 0; dp < 50; dp++) {
            unsigned long long bv = pb[dp];
            #pragma unroll
            for (int i = 0; i < 13; i++) {
                int n = warp + 8 * i; n = (n > 99) ? 99 : n;
                acc[i] = f32x2_fma(*(const unsigned long long*)(sH1 + n * 100 + 2 * dp),
                                   bv, acc[i]);
            }
        }
        __syncthreads();   // S2: all W2/h1 reads done; sT overwrites W2 region
        if (lane < 20) {
            float* sT = sW2;
            #pragma unroll
            for (int i = 0; i < 13; i++) {
                int n = warp + 8 * i;
                if (n > 99) continue;
                sT[n * 20 + lane] = f32x2_hsum(acc[i]);
            }
        }
    }
    __syncthreads();   // S3

    // ---- phase D: h2 = relu(mean_e sT[src] + b2); hg = sum_n h2 ----
    if (lane < 20) {
        const float* sT = sW2;
        float hgacc = 0.f;
        for (int n = warp; n < NPG; n += 8) {
            const unsigned char* sp = sSrc + n * DEG;
            float a = 0.f;
            #pragma unroll
            for (int e = 0; e < DEG; e++)
                a += sT[sp[e] * 20 + lane];
            hgacc += fmaxf(a * (1.f / DEG) + sB2[lane], 0.f);
        }
        atomicAdd(&shg[lane], hgacc);
    }
    __syncthreads();   // S4

    // ---- tail (warp 0): 2x (V@Wo + LN) + MLP ----
    if (warp == 0) {
        float hgk = (lane < 20) ? shg[lane] * (1.f / NPG) : 0.f;

        {
            const float4* xr = (const float4*)(self_feat + (size_t)g * 200);
            const float4* wr = (const float4*)(Wv2 + lane * 200);
            float acc = 0.f;
            #pragma unroll 5
            for (int p = 0; p < 50; p++) {
                float4 a = wr[p], b = xr[p];
                acc += a.x * b.x + a.y * b.y + a.z * b.z + a.w * b.w;
            }
            sVec[lane] = acc;
        }
        __syncwarp();
        float y = 0.f;
        if (lane < 20) {
            const float* wo = Wo2 + lane * 32;
            float z = 0.f;
            #pragma unroll
            for (int j = 0; j < 32; j++) z += wo[j] * sVec[j];
            y = hgk + z;
        }
        float s = y;
        #pragma unroll
        for (int o = 16; o; o >>= 1) s += __shfl_xor_sync(0xffffffffu, s, o);
        float mu = s * (1.f / 20.f);
        float dd = (lane < 20) ? (y - mu) : 0.f;
        float vv = dd * dd;
        #pragma unroll
        for (int o = 16; o; o >>= 1) vv += __shfl_xor_sync(0xffffffffu, vv, o);
        float hg1 = 0.f;
        if (lane < 20)
            hg1 = dd * rsqrtf(vv * (1.f / 20.f) + 1e-5f) * g2[lane] + be2[lane];

        __syncwarp();
        {
            const float4* xr = (const float4*)(x3d + (size_t)g * 100);
            const float4* wr = (const float4*)(Wv3 + lane * 100);
            float acc = 0.f;
            #pragma unroll 5
            for (int p = 0; p < 25; p++) {
                float4 a = wr[p], b = xr[p];
                acc += a.x * b.x + a.y * b.y + a.z * b.z + a.w * b.w;
            }
            sVec[lane] = acc;
        }
        __syncwarp();
        float y2 = 0.f;
        if (lane < 20) {
            const float* wo = Wo3 + lane * 32;
            float z = 0.f;
            #pragma unroll
            for (int j = 0; j < 32; j++) z += wo[j] * sVec[j];
            y2 = hg1 + z;
        }
        float s2 = y2;
        #pragma unroll
        for (int o = 16; o; o >>= 1) s2 += __shfl_xor_sync(0xffffffffu, s2, o);
        float mu2 = s2 * (1.f / 20.f);
        float d2 = (lane < 20) ? (y2 - mu2) : 0.f;
        float v2s = d2 * d2;
        #pragma unroll
        for (int o = 16; o; o >>= 1) v2s += __shfl_xor_sync(0xffffffffu, v2s, o);
        float hg2 = 0.f;
        if (lane < 20)
            hg2 = d2 * rsqrtf(v2s * (1.f / 20.f) + 1e-5f) * g3[lane] + be3[lane];

        __syncwarp();
        if (lane < 20) sVec[lane] = hg2;
        __syncwarp();

        float f = 0.f;
        if (lane < 10) {
            const float* wf = Wf1 + lane * 20;
            float a = bf1[lane];
            #pragma unroll
            for (int k = 0; k < 20; k++) a += wf[k] * sVec[k];
            f = fmaxf(a, 0.f) * Wf2[lane];
        }
        #pragma unroll
        for (int o = 16; o; o >>= 1) f += __shfl_xor_sync(0xffffffffu, f, o);
        if (lane == 0) out[g] = f + bf2[0];
    }
}

// ============================ launch ============================
extern "C" void kernel_launch(void* const* d_in, const int* in_sizes, int n_in,
                              void* d_out, int out_size) {
    const float* feat      = (const float*)d_in[0];
    const int*   edge_src  = (const int*)  d_in[1];
    // d_in[2] = edge_dst: repeat(arange(N), DEG) by construction — implicit
    const float* self_feat = (const float*)d_in[3];
    const float* x3d       = (const float*)d_in[4];
    const float* W1  = (const float*)d_in[5];
    const float* b1  = (const float*)d_in[6];
    const float* W2  = (const float*)d_in[7];
    const float* b2  = (const float*)d_in[8];
    const float* Wv2 = (const float*)d_in[11];
    const float* Wo2 = (const float*)d_in[12];
    const float* g2  = (const float*)d_in[13];
    const float* be2 = (const float*)d_in[14];
    const float* Wv3 = (const float*)d_in[17];
    const float* Wo3 = (const float*)d_in[18];
    const float* g3  = (const float*)d_in[19];
    const float* be3 = (const float*)d_in[20];
    const float* Wf1 = (const float*)d_in[21];
    const float* bf1 = (const float*)d_in[22];
    const float* Wf2 = (const float*)d_in[23];
    const float* bf2 = (const float*)d_in[24];

    cudaFuncSetAttribute(gemm1_kernel,
                         cudaFuncAttributeMaxDynamicSharedMemorySize,
                         (int)K1_SMEM);
    gemm1_kernel<<<NNODES / 128, BLK, K1_SMEM>>>(feat, W1);

    const size_t k2_smem = (size_t)K2_FLOATS * sizeof(float);
    cudaFuncSetAttribute(gnn_rest_kernel,
                         cudaFuncAttributeMaxDynamicSharedMemorySize,
                         (int)k2_smem);
    gnn_rest_kernel<<<NGRAPH, BLK, k2_smem>>>(
        edge_src, self_feat, x3d,
        b1, W2, b2,
        Wv2, Wo2, g2, be2,
        Wv3, Wo3, g3, be3,
        Wf1, bf1, Wf2, bf2,
        (float*)d_out);
}